// round 6
// baseline (speedup 1.0000x reference)
#include <cuda_runtime.h>
#include <cuda_fp16.h>
#include <math.h>

#define NN 100000
#define EE 1600000
#define HH 128
#define GG 128
#define LL 3
#define BN_EPS 1e-5f

#define SCAN_CHUNK 1024
#define SCAN_BLOCKS ((NN + SCAN_CHUNK - 1) / SCAN_CHUNK)   // 98

#define APAD 136                       // padded row length in halves (conflict-free)
#define GEMM_SMEM (2 * 128 * APAD * 2) // 69632 bytes

// ---------------- scratch (device globals; no allocation) ----------------
__device__ int   g_deg[NN];
__device__ int   g_fill[NN];
__device__ int   g_rowptr[NN + 1];
__device__ int   g_colidx[EE];
__device__ int   g_gstart[GG + 1];
__device__ int   g_bsum[SCAN_BLOCKS];
__device__ float g_dinv[NN];
__device__ __half2 g_x16[(size_t)NN * HH / 2];  // fp16 input features
__device__ __half2 g_t[(size_t)NN * HH / 2];    // post-GEMM features (fp16)
__device__ __half2 g_h16[(size_t)NN * HH / 2];  // post-SpMM activations (fp16)
__device__ __half  g_w16t[(size_t)LL * HH * HH]; // W transposed [l][n][k] fp16

// ---------------- CSR build ----------------
__global__ void init_kernel() {
    int i = blockIdx.x * blockDim.x + threadIdx.x;
    if (i < NN) { g_deg[i] = 1; g_fill[i] = 0; }   // self-loop counts 1
}

__global__ void count_kernel(const int* __restrict__ dst) {
    int e = blockIdx.x * blockDim.x + threadIdx.x;
    if (e < EE) atomicAdd(&g_deg[dst[e]], 1);
}

__global__ void dinv_kernel() {
    int i = blockIdx.x * blockDim.x + threadIdx.x;
    if (i < NN) g_dinv[i] = rsqrtf((float)g_deg[i]);
}

__device__ __forceinline__ int warp_incl_scan(int v, unsigned lane) {
#pragma unroll
    for (int o = 1; o < 32; o <<= 1) {
        int t = __shfl_up_sync(0xffffffffu, v, o);
        if (lane >= o) v += t;
    }
    return v;
}

__global__ void scan_reduce_kernel() {
    __shared__ int wsum[32];
    int tid = threadIdx.x;
    unsigned lane = tid & 31;
    int wid = tid >> 5;
    int i = blockIdx.x * SCAN_CHUNK + tid;
    int v = (i < NN) ? (g_deg[i] - 1) : 0;
#pragma unroll
    for (int o = 16; o > 0; o >>= 1) v += __shfl_down_sync(0xffffffffu, v, o);
    if (lane == 0) wsum[wid] = v;
    __syncthreads();
    if (wid == 0) {
        int w = wsum[lane];
#pragma unroll
        for (int o = 16; o > 0; o >>= 1) w += __shfl_down_sync(0xffffffffu, w, o);
        if (lane == 0) g_bsum[blockIdx.x] = w;
    }
}

__global__ void scan_spine_kernel() {
    __shared__ int wtot[4];
    int tid = threadIdx.x;              // 0..127
    unsigned lane = tid & 31;
    int wid = tid >> 5;
    int v = (tid < SCAN_BLOCKS) ? g_bsum[tid] : 0;
    int incl = warp_incl_scan(v, lane);
    if (lane == 31) wtot[wid] = incl;
    __syncthreads();
    int off = 0;
    for (int w = 0; w < wid; w++) off += wtot[w];
    if (tid < SCAN_BLOCKS) g_bsum[tid] = off + incl - v;   // exclusive
    if (tid == 127) g_rowptr[NN] = off + incl;             // grand total
}

__global__ void scan_apply_kernel() {
    __shared__ int wsum[32];
    int tid = threadIdx.x;
    unsigned lane = tid & 31;
    int wid = tid >> 5;
    int i = blockIdx.x * SCAN_CHUNK + tid;
    int v = (i < NN) ? (g_deg[i] - 1) : 0;
    int incl = warp_incl_scan(v, lane);
    if (lane == 31) wsum[wid] = incl;
    __syncthreads();
    int woff = 0;
    for (int w = 0; w < wid; w++) woff += wsum[w];
    if (i < NN) g_rowptr[i] = g_bsum[blockIdx.x] + woff + incl - v;
}

__global__ void scatter_kernel(const int* __restrict__ src, const int* __restrict__ dst) {
    int e = blockIdx.x * blockDim.x + threadIdx.x;
    if (e < EE) {
        int d = dst[e];
        int p = g_rowptr[d] + atomicAdd(&g_fill[d], 1);
        g_colidx[p] = src[e];
    }
}

__global__ void bounds_kernel(const int* __restrict__ batch) {
    int g = blockIdx.x * blockDim.x + threadIdx.x;
    if (g > GG) return;
    int lo = 0, hi = NN;
    while (lo < hi) {
        int m = (lo + hi) >> 1;
        if (batch[m] < g) lo = m + 1; else hi = m;
    }
    g_gstart[g] = lo;
}

// ---------------- conversions ----------------
__global__ void convert_x_kernel(const float* __restrict__ x) {
    int i = blockIdx.x * blockDim.x + threadIdx.x;
    if (i < NN * HH / 2) {
        float2 f = ((const float2*)x)[i];
        g_x16[i] = __floats2half2_rn(f.x, f.y);
    }
}

__global__ void convert_w_kernel(const float* __restrict__ Ws) {
    int i = blockIdx.x * blockDim.x + threadIdx.x;   // 0..HH*HH-1
    int l = blockIdx.y;
    if (i < HH * HH) {
        int k = i >> 7, n = i & 127;
        g_w16t[(size_t)l * HH * HH + n * HH + k] = __float2half(Ws[(size_t)l * HH * HH + i]);
    }
}

// ---------------- tensor-core GEMM: C[n,128](fp16) = A[n,128](fp16) @ W ----------------
extern __shared__ __align__(16) char gemm_smem[];

__global__ void __launch_bounds__(256)
gemm_mma_kernel(const __half* __restrict__ A, const __half* __restrict__ Wt,
                __half2* __restrict__ C2, int n) {
    __half* As = (__half*)gemm_smem;                       // [128][APAD]
    __half* Bs = (__half*)(gemm_smem + 128 * APAD * 2);    // [128][APAD] (Wt: [n][k])

    int tid = threadIdx.x;
    int r0 = blockIdx.x * 128;

    const uint4* Ag = (const uint4*)A;
    const uint4* Wg = (const uint4*)Wt;
    uint4* As4 = (uint4*)As;
    uint4* Bs4 = (uint4*)Bs;
#pragma unroll
    for (int i = 0; i < 8; i++) {
        int lin = tid + i * 256;          // 0..2047
        int row = lin >> 4, c = lin & 15;
        uint4 v = make_uint4(0, 0, 0, 0);
        if (r0 + row < n) v = Ag[(size_t)(r0 + row) * 16 + c];
        As4[row * 17 + c] = v;
        Bs4[row * 17 + c] = Wg[row * 16 + c];
    }
    __syncthreads();

    int lane = tid & 31, warp = tid >> 5;
    int wm = (warp & 3) * 32;
    int wn = (warp >> 2) * 64;
    int g = lane >> 2, tg = lane & 3;

    float c[2][8][4];
#pragma unroll
    for (int mt = 0; mt < 2; mt++)
#pragma unroll
        for (int nt = 0; nt < 8; nt++)
#pragma unroll
            for (int q = 0; q < 4; q++) c[mt][nt][q] = 0.f;

#pragma unroll
    for (int ks = 0; ks < 8; ks++) {
        int k0 = ks * 16;
        unsigned a[2][4];
#pragma unroll
        for (int mt = 0; mt < 2; mt++) {
            int rb = wm + mt * 16;
            const __half* p0 = As + (rb + g) * APAD + k0 + tg * 2;
            const __half* p1 = As + (rb + g + 8) * APAD + k0 + tg * 2;
            a[mt][0] = *(const unsigned*)p0;
            a[mt][1] = *(const unsigned*)p1;
            a[mt][2] = *(const unsigned*)(p0 + 8);
            a[mt][3] = *(const unsigned*)(p1 + 8);
        }
#pragma unroll
        for (int nt = 0; nt < 8; nt++) {
            int nrow = wn + nt * 8 + g;
            const __half* q = Bs + nrow * APAD + k0 + tg * 2;
            unsigned b0 = *(const unsigned*)q;
            unsigned b1 = *(const unsigned*)(q + 8);
#pragma unroll
            for (int mt = 0; mt < 2; mt++) {
                asm volatile(
                    "mma.sync.aligned.m16n8k16.row.col.f32.f16.f16.f32 "
                    "{%0,%1,%2,%3}, {%4,%5,%6,%7}, {%8,%9}, {%0,%1,%2,%3};"
                    : "+f"(c[mt][nt][0]), "+f"(c[mt][nt][1]),
                      "+f"(c[mt][nt][2]), "+f"(c[mt][nt][3])
                    : "r"(a[mt][0]), "r"(a[mt][1]), "r"(a[mt][2]), "r"(a[mt][3]),
                      "r"(b0), "r"(b1));
            }
        }
    }

#pragma unroll
    for (int mt = 0; mt < 2; mt++) {
        int rb = r0 + wm + mt * 16;
#pragma unroll
        for (int nt = 0; nt < 8; nt++) {
            int col2 = ((wn + nt * 8) >> 1) + tg;
            int r_lo = rb + g, r_hi = rb + g + 8;
            if (r_lo < n) C2[(size_t)r_lo * 64 + col2] = __floats2half2_rn(c[mt][nt][0], c[mt][nt][1]);
            if (r_hi < n) C2[(size_t)r_hi * 64 + col2] = __floats2half2_rn(c[mt][nt][2], c[mt][nt][3]);
        }
    }
}

// ---------------- SpMM + bias + BN + ReLU ----------------
// One warp per node; lanes 0-15 process even edges, 16-31 odd edges.
// Each lane loads uint4 (8 fp16 feats); one LDG.128 fetches two full rows.
// Metadata batch-loaded 32 edges at a time, shuffle-broadcast.
__global__ void spmm_kernel(const float* __restrict__ bias, const float* __restrict__ gamma,
                            const float* __restrict__ beta, const float* __restrict__ rm,
                            const float* __restrict__ rv) {
    int warp = (blockIdx.x * blockDim.x + threadIdx.x) >> 5;
    if (warp >= NN) return;
    int lane = threadIdx.x & 31;
    int sub = lane & 15;          // feature segment: feats [sub*8, sub*8+8)
    int hi = lane >> 4;           // 0: even edges, 1: odd edges
    int v = warp;
    float dv = g_dinv[v];
    const uint4* t16 = (const uint4*)g_t;   // 16 uint4 per 128-feat row

    float acc[8];
#pragma unroll
    for (int q = 0; q < 8; q++) acc[q] = 0.f;

    // self-loop on lower half only
    if (hi == 0) {
        uint4 xs = t16[(size_t)v * 16 + sub];
        const __half2* hx = (const __half2*)&xs;
        float ws = dv * dv;
#pragma unroll
        for (int q = 0; q < 4; q++) {
            float2 f = __half22float2(hx[q]);
            acc[2 * q]     += ws * f.x;
            acc[2 * q + 1] += ws * f.y;
        }
    }

    int jb = g_rowptr[v], end = g_rowptr[v + 1];
    for (int base = jb; base < end; base += 32) {
        int myj = base + lane;
        int c = v;
        float w = 0.f;
        if (myj < end) {
            c = g_colidx[myj];
            w = g_dinv[c] * dv;
        }
        int rem = end - base; if (rem > 32) rem = 32;
        int pairs = (rem + 1) >> 1;
#pragma unroll 2
        for (int i = 0; i < pairs; i++) {
            int srcl = 2 * i + hi;                       // edge slot within this 32-block
            int   ci = __shfl_sync(0xffffffffu, c, srcl);
            float wi = __shfl_sync(0xffffffffu, w, srcl);
            uint4 xx = t16[(size_t)ci * 16 + sub];
            const __half2* hx = (const __half2*)&xx;
#pragma unroll
            for (int q = 0; q < 4; q++) {
                float2 f = __half22float2(hx[q]);
                acc[2 * q]     += wi * f.x;
                acc[2 * q + 1] += wi * f.y;
            }
        }
    }

    // combine halves
#pragma unroll
    for (int q = 0; q < 8; q++)
        acc[q] += __shfl_xor_sync(0xffffffffu, acc[q], 16);

    if (hi == 0) {
        int f0 = sub * 8;   // first feature of this lane's segment
        float4 b0 = *(const float4*)(bias  + f0);
        float4 b1 = *(const float4*)(bias  + f0 + 4);
        float4 g0 = *(const float4*)(gamma + f0);
        float4 g1 = *(const float4*)(gamma + f0 + 4);
        float4 e0 = *(const float4*)(beta  + f0);
        float4 e1 = *(const float4*)(beta  + f0 + 4);
        float4 m0 = *(const float4*)(rm    + f0);
        float4 m1 = *(const float4*)(rm    + f0 + 4);
        float4 v0 = *(const float4*)(rv    + f0);
        float4 v1 = *(const float4*)(rv    + f0 + 4);

        float o[8];
        o[0] = fmaxf((acc[0] + b0.x - m0.x) * (g0.x * rsqrtf(v0.x + BN_EPS)) + e0.x, 0.f);
        o[1] = fmaxf((acc[1] + b0.y - m0.y) * (g0.y * rsqrtf(v0.y + BN_EPS)) + e0.y, 0.f);
        o[2] = fmaxf((acc[2] + b0.z - m0.z) * (g0.z * rsqrtf(v0.z + BN_EPS)) + e0.z, 0.f);
        o[3] = fmaxf((acc[3] + b0.w - m0.w) * (g0.w * rsqrtf(v0.w + BN_EPS)) + e0.w, 0.f);
        o[4] = fmaxf((acc[4] + b1.x - m1.x) * (g1.x * rsqrtf(v1.x + BN_EPS)) + e1.x, 0.f);
        o[5] = fmaxf((acc[5] + b1.y - m1.y) * (g1.y * rsqrtf(v1.y + BN_EPS)) + e1.y, 0.f);
        o[6] = fmaxf((acc[6] + b1.z - m1.z) * (g1.z * rsqrtf(v1.z + BN_EPS)) + e1.z, 0.f);
        o[7] = fmaxf((acc[7] + b1.w - m1.w) * (g1.w * rsqrtf(v1.w + BN_EPS)) + e1.w, 0.f);

        __half2 p0 = __floats2half2_rn(o[0], o[1]);
        __half2 p1 = __floats2half2_rn(o[2], o[3]);
        __half2 p2 = __floats2half2_rn(o[4], o[5]);
        __half2 p3 = __floats2half2_rn(o[6], o[7]);
        uint4 u;
        u.x = *(unsigned*)&p0; u.y = *(unsigned*)&p1;
        u.z = *(unsigned*)&p2; u.w = *(unsigned*)&p3;
        ((uint4*)g_h16)[(size_t)v * 16 + sub] = u;
    }
}

// ---------------- pool + LSTM + FC (block per graph) ----------------
__device__ __forceinline__ float sigmoidf_(float x) { return 1.f / (1.f + expf(-x)); }

__global__ void pool_lstm_kernel(const float* __restrict__ W_ih, const float* __restrict__ b_ih,
                                 const float* __restrict__ b_hh, const float* __restrict__ W_fc,
                                 const float* __restrict__ b_fc, float* __restrict__ out) {
    int g = blockIdx.x;
    int j = threadIdx.x;  // 0..127
    __shared__ __align__(16) float p[HH];
    __shared__ __align__(16) float hn[HH];

    const __half* hb = (const __half*)g_h16;
    int s = g_gstart[g], e = g_gstart[g + 1];
    float sum = 0.f;
    int n = s;
    for (; n + 3 < e; n += 4) {
        sum += __half2float(hb[(size_t)n * HH + j]) + __half2float(hb[(size_t)(n + 1) * HH + j])
             + __half2float(hb[(size_t)(n + 2) * HH + j]) + __half2float(hb[(size_t)(n + 3) * HH + j]);
    }
    for (; n < e; ++n) sum += __half2float(hb[(size_t)n * HH + j]);
    float cnt = (float)((e - s) > 0 ? (e - s) : 1);
    p[j] = sum / cnt;
    __syncthreads();

    float gate[4];
#pragma unroll
    for (int q = 0; q < 4; q++) {
        const float4* wr = (const float4*)(W_ih + (size_t)(q * HH + j) * HH);
        const float4* pp = (const float4*)p;
        float a = 0.f;
#pragma unroll
        for (int k = 0; k < 32; k++) {
            float4 w = wr[k];
            float4 x = pp[k];
            a += w.x * x.x + w.y * x.y + w.z * x.z + w.w * x.w;
        }
        gate[q] = a + b_ih[q * HH + j] + b_hh[q * HH + j];
    }
    float iv = sigmoidf_(gate[0]);
    float gv = tanhf(gate[2]);
    float ov = sigmoidf_(gate[3]);
    float c = iv * gv;
    hn[j] = ov * tanhf(c);
    __syncthreads();

    if (j < 16) {
        const float4* wr = (const float4*)(W_fc + (size_t)j * HH);
        const float4* hh = (const float4*)hn;
        float a = b_fc[j];
#pragma unroll
        for (int k = 0; k < 32; k++) {
            float4 w = wr[k];
            float4 x = hh[k];
            a += w.x * x.x + w.y * x.y + w.z * x.z + w.w * x.w;
        }
        out[g * 16 + j] = a;
    }
}

// ---------------- host-side symbol address helpers ----------------
static __half* get_x16_ptr() {
    static __half* p = nullptr;
    if (!p) cudaGetSymbolAddress((void**)&p, g_x16);
    return p;
}
static __half* get_h16_ptr() {
    static __half* p = nullptr;
    if (!p) cudaGetSymbolAddress((void**)&p, g_h16);
    return p;
}
static __half2* get_t_ptr() {
    static __half2* p = nullptr;
    if (!p) cudaGetSymbolAddress((void**)&p, g_t);
    return p;
}
static __half* get_w16t_ptr() {
    static __half* p = nullptr;
    if (!p) cudaGetSymbolAddress((void**)&p, g_w16t);
    return p;
}

// ---------------- launch ----------------
extern "C" void kernel_launch(void* const* d_in, const int* in_sizes, int n_in,
                              void* d_out, int out_size) {
    const float* x     = (const float*)d_in[0];
    const int*   eidx  = (const int*)d_in[1];      // [2, E]
    const int*   batch = (const int*)d_in[2];
    const float* Ws    = (const float*)d_in[3];    // [3,128,128]
    const float* bs    = (const float*)d_in[4];
    const float* gam   = (const float*)d_in[5];
    const float* bet   = (const float*)d_in[6];
    const float* rms   = (const float*)d_in[7];
    const float* rvs   = (const float*)d_in[8];
    const float* W_ih  = (const float*)d_in[9];
    // d_in[10] = W_hh (unused: h0 = c0 = 0)
    const float* b_ih  = (const float*)d_in[11];
    const float* b_hh  = (const float*)d_in[12];
    const float* W_fc  = (const float*)d_in[13];
    const float* b_fc  = (const float*)d_in[14];
    float* out = (float*)d_out;

    const int* src = eidx;
    const int* dst = eidx + EE;

    __half*  x16   = get_x16_ptr();
    __half*  h16   = get_h16_ptr();
    __half2* t_ptr = get_t_ptr();
    __half*  w16t  = get_w16t_ptr();

    static cudaStream_t s2 = nullptr;
    static cudaEvent_t ev_fork = nullptr, ev_join = nullptr;
    if (!s2) {
        cudaStreamCreateWithFlags(&s2, cudaStreamNonBlocking);
        cudaEventCreateWithFlags(&ev_fork, cudaEventDisableTiming);
        cudaEventCreateWithFlags(&ev_join, cudaEventDisableTiming);
        cudaFuncSetAttribute(gemm_mma_kernel,
                             cudaFuncAttributeMaxDynamicSharedMemorySize, GEMM_SMEM);
    }

    // fork: CSR build chain on s2
    cudaEventRecord(ev_fork, 0);
    cudaStreamWaitEvent(s2, ev_fork, 0);

    init_kernel<<<(NN + 255) / 256, 256, 0, s2>>>();
    count_kernel<<<(EE + 255) / 256, 256, 0, s2>>>(dst);
    dinv_kernel<<<(NN + 255) / 256, 256, 0, s2>>>();
    scan_reduce_kernel<<<SCAN_BLOCKS, SCAN_CHUNK, 0, s2>>>();
    scan_spine_kernel<<<1, 128, 0, s2>>>();
    scan_apply_kernel<<<SCAN_BLOCKS, SCAN_CHUNK, 0, s2>>>();
    scatter_kernel<<<(EE + 255) / 256, 256, 0, s2>>>(src, dst);
    bounds_kernel<<<1, 256, 0, s2>>>(batch);
    cudaEventRecord(ev_join, s2);

    // main stream: conversions + layer pipeline
    {
        dim3 wgrid((HH * HH + 255) / 256, LL);
        convert_w_kernel<<<wgrid, 256>>>(Ws);
    }
    convert_x_kernel<<<(NN * HH / 2 + 255) / 256, 256>>>(x);

    int gemm_blocks = (NN + 127) / 128;
    int spmm_blocks = (NN * 32 + 255) / 256;

    gemm_mma_kernel<<<gemm_blocks, 256, GEMM_SMEM>>>(x16, w16t, t_ptr, NN);
    cudaStreamWaitEvent(0, ev_join, 0);                       // join CSR build
    spmm_kernel<<<spmm_blocks, 256>>>(bs, gam, bet, rms, rvs);

    for (int l = 1; l < LL; l++) {
        gemm_mma_kernel<<<gemm_blocks, 256, GEMM_SMEM>>>(h16, w16t + (size_t)l * HH * HH,
                                                         t_ptr, NN);
        spmm_kernel<<<spmm_blocks, 256>>>(bs + l * HH, gam + l * HH, bet + l * HH,
                                          rms + l * HH, rvs + l * HH);
    }
    pool_lstm_kernel<<<GG, 128>>>(W_ih, b_ih, b_hh, W_fc, b_fc, out);
}

// round 7
// speedup vs baseline: 1.2592x; 1.2592x over previous
#include <cuda_runtime.h>
#include <cuda_fp16.h>
#include <math.h>

#define NN 100000
#define EE 1600000
#define HH 128
#define GG 128
#define LL 3
#define BN_EPS 1e-5f

#define SCAN_CHUNK 1024
#define SCAN_BLOCKS ((NN + SCAN_CHUNK - 1) / SCAN_CHUNK)   // 98

#define APAD 136                       // padded row length in halves (conflict-free)
#define GEMM_SMEM (2 * 128 * APAD * 2) // 69632 bytes

// ---------------- scratch (device globals; no allocation) ----------------
__device__ int   g_deg[NN];
__device__ int   g_fill[NN];
__device__ int   g_rowptr[NN + 1];
__device__ int   g_colidx[EE];
__device__ int   g_gstart[GG + 1];
__device__ int   g_bsum[SCAN_BLOCKS];
__device__ float g_dinv[NN];
__device__ __half2 g_x16[(size_t)NN * HH / 2];  // fp16 input features
__device__ __half2 g_t[(size_t)NN * HH / 2];    // post-GEMM features (fp16)
__device__ __half2 g_h16[(size_t)NN * HH / 2];  // post-SpMM activations (fp16)
__device__ __half  g_w16t[(size_t)LL * HH * HH]; // W transposed [l][n][k] fp16

// ---------------- CSR build ----------------
__global__ void init_kernel() {
    int i = blockIdx.x * blockDim.x + threadIdx.x;
    if (i < NN) { g_deg[i] = 1; g_fill[i] = 0; }   // self-loop counts 1
}

__global__ void count_kernel(const int* __restrict__ dst) {
    int e = blockIdx.x * blockDim.x + threadIdx.x;
    if (e < EE) atomicAdd(&g_deg[dst[e]], 1);
}

__global__ void dinv_kernel() {
    int i = blockIdx.x * blockDim.x + threadIdx.x;
    if (i < NN) g_dinv[i] = rsqrtf((float)g_deg[i]);
}

__device__ __forceinline__ int warp_incl_scan(int v, unsigned lane) {
#pragma unroll
    for (int o = 1; o < 32; o <<= 1) {
        int t = __shfl_up_sync(0xffffffffu, v, o);
        if (lane >= o) v += t;
    }
    return v;
}

__global__ void scan_reduce_kernel() {
    __shared__ int wsum[32];
    int tid = threadIdx.x;
    unsigned lane = tid & 31;
    int wid = tid >> 5;
    int i = blockIdx.x * SCAN_CHUNK + tid;
    int v = (i < NN) ? (g_deg[i] - 1) : 0;
#pragma unroll
    for (int o = 16; o > 0; o >>= 1) v += __shfl_down_sync(0xffffffffu, v, o);
    if (lane == 0) wsum[wid] = v;
    __syncthreads();
    if (wid == 0) {
        int w = wsum[lane];
#pragma unroll
        for (int o = 16; o > 0; o >>= 1) w += __shfl_down_sync(0xffffffffu, w, o);
        if (lane == 0) g_bsum[blockIdx.x] = w;
    }
}

__global__ void scan_spine_kernel() {
    __shared__ int wtot[4];
    int tid = threadIdx.x;              // 0..127
    unsigned lane = tid & 31;
    int wid = tid >> 5;
    int v = (tid < SCAN_BLOCKS) ? g_bsum[tid] : 0;
    int incl = warp_incl_scan(v, lane);
    if (lane == 31) wtot[wid] = incl;
    __syncthreads();
    int off = 0;
    for (int w = 0; w < wid; w++) off += wtot[w];
    if (tid < SCAN_BLOCKS) g_bsum[tid] = off + incl - v;   // exclusive
    if (tid == 127) g_rowptr[NN] = off + incl;             // grand total
}

__global__ void scan_apply_kernel() {
    __shared__ int wsum[32];
    int tid = threadIdx.x;
    unsigned lane = tid & 31;
    int wid = tid >> 5;
    int i = blockIdx.x * SCAN_CHUNK + tid;
    int v = (i < NN) ? (g_deg[i] - 1) : 0;
    int incl = warp_incl_scan(v, lane);
    if (lane == 31) wsum[wid] = incl;
    __syncthreads();
    int woff = 0;
    for (int w = 0; w < wid; w++) woff += wsum[w];
    if (i < NN) g_rowptr[i] = g_bsum[blockIdx.x] + woff + incl - v;
}

__global__ void scatter_kernel(const int* __restrict__ src, const int* __restrict__ dst) {
    int e = blockIdx.x * blockDim.x + threadIdx.x;
    if (e < EE) {
        int d = dst[e];
        int p = g_rowptr[d] + atomicAdd(&g_fill[d], 1);
        g_colidx[p] = src[e];
    }
}

__global__ void bounds_kernel(const int* __restrict__ batch) {
    int g = blockIdx.x * blockDim.x + threadIdx.x;
    if (g > GG) return;
    int lo = 0, hi = NN;
    while (lo < hi) {
        int m = (lo + hi) >> 1;
        if (batch[m] < g) lo = m + 1; else hi = m;
    }
    g_gstart[g] = lo;
}

// ---------------- conversions ----------------
__global__ void convert_x_kernel(const float* __restrict__ x) {
    int i = blockIdx.x * blockDim.x + threadIdx.x;
    if (i < NN * HH / 2) {
        float2 f = ((const float2*)x)[i];
        g_x16[i] = __floats2half2_rn(f.x, f.y);
    }
}

__global__ void convert_w_kernel(const float* __restrict__ Ws) {
    int i = blockIdx.x * blockDim.x + threadIdx.x;   // 0..HH*HH-1
    int l = blockIdx.y;
    if (i < HH * HH) {
        int k = i >> 7, n = i & 127;
        g_w16t[(size_t)l * HH * HH + n * HH + k] = __float2half(Ws[(size_t)l * HH * HH + i]);
    }
}

// ---------------- tensor-core GEMM: C[n,128](fp16) = A[n,128](fp16) @ W ----------------
extern __shared__ __align__(16) char gemm_smem[];

__global__ void __launch_bounds__(256)
gemm_mma_kernel(const __half* __restrict__ A, const __half* __restrict__ Wt,
                __half2* __restrict__ C2, int n) {
    __half* As = (__half*)gemm_smem;                       // [128][APAD]
    __half* Bs = (__half*)(gemm_smem + 128 * APAD * 2);    // [128][APAD] (Wt: [n][k])

    int tid = threadIdx.x;
    int r0 = blockIdx.x * 128;

    const uint4* Ag = (const uint4*)A;
    const uint4* Wg = (const uint4*)Wt;
    uint4* As4 = (uint4*)As;
    uint4* Bs4 = (uint4*)Bs;
#pragma unroll
    for (int i = 0; i < 8; i++) {
        int lin = tid + i * 256;          // 0..2047
        int row = lin >> 4, c = lin & 15;
        uint4 v = make_uint4(0, 0, 0, 0);
        if (r0 + row < n) v = Ag[(size_t)(r0 + row) * 16 + c];
        As4[row * 17 + c] = v;
        Bs4[row * 17 + c] = Wg[row * 16 + c];
    }
    __syncthreads();

    int lane = tid & 31, warp = tid >> 5;
    int wm = (warp & 3) * 32;
    int wn = (warp >> 2) * 64;
    int g = lane >> 2, tg = lane & 3;

    float c[2][8][4];
#pragma unroll
    for (int mt = 0; mt < 2; mt++)
#pragma unroll
        for (int nt = 0; nt < 8; nt++)
#pragma unroll
            for (int q = 0; q < 4; q++) c[mt][nt][q] = 0.f;

#pragma unroll
    for (int ks = 0; ks < 8; ks++) {
        int k0 = ks * 16;
        unsigned a[2][4];
#pragma unroll
        for (int mt = 0; mt < 2; mt++) {
            int rb = wm + mt * 16;
            const __half* p0 = As + (rb + g) * APAD + k0 + tg * 2;
            const __half* p1 = As + (rb + g + 8) * APAD + k0 + tg * 2;
            a[mt][0] = *(const unsigned*)p0;
            a[mt][1] = *(const unsigned*)p1;
            a[mt][2] = *(const unsigned*)(p0 + 8);
            a[mt][3] = *(const unsigned*)(p1 + 8);
        }
#pragma unroll
        for (int nt = 0; nt < 8; nt++) {
            int nrow = wn + nt * 8 + g;
            const __half* q = Bs + nrow * APAD + k0 + tg * 2;
            unsigned b0 = *(const unsigned*)q;
            unsigned b1 = *(const unsigned*)(q + 8);
#pragma unroll
            for (int mt = 0; mt < 2; mt++) {
                asm volatile(
                    "mma.sync.aligned.m16n8k16.row.col.f32.f16.f16.f32 "
                    "{%0,%1,%2,%3}, {%4,%5,%6,%7}, {%8,%9}, {%0,%1,%2,%3};"
                    : "+f"(c[mt][nt][0]), "+f"(c[mt][nt][1]),
                      "+f"(c[mt][nt][2]), "+f"(c[mt][nt][3])
                    : "r"(a[mt][0]), "r"(a[mt][1]), "r"(a[mt][2]), "r"(a[mt][3]),
                      "r"(b0), "r"(b1));
            }
        }
    }

#pragma unroll
    for (int mt = 0; mt < 2; mt++) {
        int rb = r0 + wm + mt * 16;
#pragma unroll
        for (int nt = 0; nt < 8; nt++) {
            int col2 = ((wn + nt * 8) >> 1) + tg;
            int r_lo = rb + g, r_hi = rb + g + 8;
            if (r_lo < n) C2[(size_t)r_lo * 64 + col2] = __floats2half2_rn(c[mt][nt][0], c[mt][nt][1]);
            if (r_hi < n) C2[(size_t)r_hi * 64 + col2] = __floats2half2_rn(c[mt][nt][2], c[mt][nt][3]);
        }
    }
}

// ---------------- SpMM + bias + BN + ReLU (warp per node, fp16 gathers) ----------------
// R5 structure restored (independent LDG.64 gathers), unrolled to 8 edges in flight.
__global__ void spmm_kernel(const float* __restrict__ bias, const float* __restrict__ gamma,
                            const float* __restrict__ beta, const float* __restrict__ rm,
                            const float* __restrict__ rv) {
    int warp = (blockIdx.x * blockDim.x + threadIdx.x) >> 5;
    if (warp >= NN) return;
    int lane = threadIdx.x & 31;
    int v = warp;
    float dv = g_dinv[v];
    const uint2* t8 = (const uint2*)g_t;   // 8 bytes = 4 fp16 features

    uint2 xs = t8[(size_t)v * 32 + lane];
    float2 f01 = __half22float2(*(__half2*)&xs.x);
    float2 f23 = __half22float2(*(__half2*)&xs.y);
    float ws = dv * dv;
    float4 acc = make_float4(ws * f01.x, ws * f01.y, ws * f23.x, ws * f23.y);

    int j = g_rowptr[v], end = g_rowptr[v + 1];
    // 8-deep unroll: 8 independent gathers in flight
    for (; j + 7 < end; j += 8) {
        int c0 = g_colidx[j],     c1 = g_colidx[j + 1], c2 = g_colidx[j + 2], c3 = g_colidx[j + 3];
        int c4 = g_colidx[j + 4], c5 = g_colidx[j + 5], c6 = g_colidx[j + 6], c7 = g_colidx[j + 7];
        float w0 = g_dinv[c0] * dv, w1 = g_dinv[c1] * dv, w2 = g_dinv[c2] * dv, w3 = g_dinv[c3] * dv;
        float w4 = g_dinv[c4] * dv, w5 = g_dinv[c5] * dv, w6 = g_dinv[c6] * dv, w7 = g_dinv[c7] * dv;
        uint2 x0 = t8[(size_t)c0 * 32 + lane];
        uint2 x1 = t8[(size_t)c1 * 32 + lane];
        uint2 x2 = t8[(size_t)c2 * 32 + lane];
        uint2 x3 = t8[(size_t)c3 * 32 + lane];
        uint2 x4 = t8[(size_t)c4 * 32 + lane];
        uint2 x5 = t8[(size_t)c5 * 32 + lane];
        uint2 x6 = t8[(size_t)c6 * 32 + lane];
        uint2 x7 = t8[(size_t)c7 * 32 + lane];
        float2 a0 = __half22float2(*(__half2*)&x0.x), b0 = __half22float2(*(__half2*)&x0.y);
        float2 a1 = __half22float2(*(__half2*)&x1.x), b1 = __half22float2(*(__half2*)&x1.y);
        float2 a2 = __half22float2(*(__half2*)&x2.x), b2 = __half22float2(*(__half2*)&x2.y);
        float2 a3 = __half22float2(*(__half2*)&x3.x), b3 = __half22float2(*(__half2*)&x3.y);
        float2 a4 = __half22float2(*(__half2*)&x4.x), b4 = __half22float2(*(__half2*)&x4.y);
        float2 a5 = __half22float2(*(__half2*)&x5.x), b5 = __half22float2(*(__half2*)&x5.y);
        float2 a6 = __half22float2(*(__half2*)&x6.x), b6 = __half22float2(*(__half2*)&x6.y);
        float2 a7 = __half22float2(*(__half2*)&x7.x), b7 = __half22float2(*(__half2*)&x7.y);
        acc.x += w0 * a0.x + w1 * a1.x + w2 * a2.x + w3 * a3.x
               + w4 * a4.x + w5 * a5.x + w6 * a6.x + w7 * a7.x;
        acc.y += w0 * a0.y + w1 * a1.y + w2 * a2.y + w3 * a3.y
               + w4 * a4.y + w5 * a5.y + w6 * a6.y + w7 * a7.y;
        acc.z += w0 * b0.x + w1 * b1.x + w2 * b2.x + w3 * b3.x
               + w4 * b4.x + w5 * b5.x + w6 * b6.x + w7 * b7.x;
        acc.w += w0 * b0.y + w1 * b1.y + w2 * b2.y + w3 * b3.y
               + w4 * b4.y + w5 * b5.y + w6 * b6.y + w7 * b7.y;
    }
    for (; j + 3 < end; j += 4) {
        int c0 = g_colidx[j], c1 = g_colidx[j + 1], c2 = g_colidx[j + 2], c3 = g_colidx[j + 3];
        float w0 = g_dinv[c0] * dv, w1 = g_dinv[c1] * dv, w2 = g_dinv[c2] * dv, w3 = g_dinv[c3] * dv;
        uint2 x0 = t8[(size_t)c0 * 32 + lane];
        uint2 x1 = t8[(size_t)c1 * 32 + lane];
        uint2 x2 = t8[(size_t)c2 * 32 + lane];
        uint2 x3 = t8[(size_t)c3 * 32 + lane];
        float2 a0 = __half22float2(*(__half2*)&x0.x), b0 = __half22float2(*(__half2*)&x0.y);
        float2 a1 = __half22float2(*(__half2*)&x1.x), b1 = __half22float2(*(__half2*)&x1.y);
        float2 a2 = __half22float2(*(__half2*)&x2.x), b2 = __half22float2(*(__half2*)&x2.y);
        float2 a3 = __half22float2(*(__half2*)&x3.x), b3 = __half22float2(*(__half2*)&x3.y);
        acc.x += w0 * a0.x + w1 * a1.x + w2 * a2.x + w3 * a3.x;
        acc.y += w0 * a0.y + w1 * a1.y + w2 * a2.y + w3 * a3.y;
        acc.z += w0 * b0.x + w1 * b1.x + w2 * b2.x + w3 * b3.x;
        acc.w += w0 * b0.y + w1 * b1.y + w2 * b2.y + w3 * b3.y;
    }
    for (; j < end; ++j) {
        int cc = g_colidx[j];
        float w = g_dinv[cc] * dv;
        uint2 xx = t8[(size_t)cc * 32 + lane];
        float2 a = __half22float2(*(__half2*)&xx.x);
        float2 b = __half22float2(*(__half2*)&xx.y);
        acc.x += w * a.x; acc.y += w * a.y; acc.z += w * b.x; acc.w += w * b.y;
    }

    float4 b  = *(const float4*)(bias  + lane * 4);
    float4 gm = *(const float4*)(gamma + lane * 4);
    float4 bt = *(const float4*)(beta  + lane * 4);
    float4 m  = *(const float4*)(rm    + lane * 4);
    float4 vv = *(const float4*)(rv    + lane * 4);

    float s0 = gm.x * rsqrtf(vv.x + BN_EPS);
    float s1 = gm.y * rsqrtf(vv.y + BN_EPS);
    float s2 = gm.z * rsqrtf(vv.z + BN_EPS);
    float s3 = gm.w * rsqrtf(vv.w + BN_EPS);

    float o0 = fmaxf((acc.x + b.x - m.x) * s0 + bt.x, 0.f);
    float o1 = fmaxf((acc.y + b.y - m.y) * s1 + bt.y, 0.f);
    float o2 = fmaxf((acc.z + b.z - m.z) * s2 + bt.z, 0.f);
    float o3 = fmaxf((acc.w + b.w - m.w) * s3 + bt.w, 0.f);

    __half2 p0 = __floats2half2_rn(o0, o1);
    __half2 p1 = __floats2half2_rn(o2, o3);
    uint2 u; u.x = *(unsigned*)&p0; u.y = *(unsigned*)&p1;
    ((uint2*)g_h16)[(size_t)v * 32 + lane] = u;
}

// ---------------- pool + LSTM + FC (block per graph) ----------------
__device__ __forceinline__ float sigmoidf_(float x) { return 1.f / (1.f + expf(-x)); }

__global__ void pool_lstm_kernel(const float* __restrict__ W_ih, const float* __restrict__ b_ih,
                                 const float* __restrict__ b_hh, const float* __restrict__ W_fc,
                                 const float* __restrict__ b_fc, float* __restrict__ out) {
    int g = blockIdx.x;
    int j = threadIdx.x;  // 0..127
    __shared__ __align__(16) float p[HH];
    __shared__ __align__(16) float hn[HH];

    const __half* hb = (const __half*)g_h16;
    int s = g_gstart[g], e = g_gstart[g + 1];
    float sum = 0.f;
    int n = s;
    for (; n + 3 < e; n += 4) {
        sum += __half2float(hb[(size_t)n * HH + j]) + __half2float(hb[(size_t)(n + 1) * HH + j])
             + __half2float(hb[(size_t)(n + 2) * HH + j]) + __half2float(hb[(size_t)(n + 3) * HH + j]);
    }
    for (; n < e; ++n) sum += __half2float(hb[(size_t)n * HH + j]);
    float cnt = (float)((e - s) > 0 ? (e - s) : 1);
    p[j] = sum / cnt;
    __syncthreads();

    float gate[4];
#pragma unroll
    for (int q = 0; q < 4; q++) {
        const float4* wr = (const float4*)(W_ih + (size_t)(q * HH + j) * HH);
        const float4* pp = (const float4*)p;
        float a = 0.f;
#pragma unroll
        for (int k = 0; k < 32; k++) {
            float4 w = wr[k];
            float4 x = pp[k];
            a += w.x * x.x + w.y * x.y + w.z * x.z + w.w * x.w;
        }
        gate[q] = a + b_ih[q * HH + j] + b_hh[q * HH + j];
    }
    float iv = sigmoidf_(gate[0]);
    float gv = tanhf(gate[2]);
    float ov = sigmoidf_(gate[3]);
    float c = iv * gv;
    hn[j] = ov * tanhf(c);
    __syncthreads();

    if (j < 16) {
        const float4* wr = (const float4*)(W_fc + (size_t)j * HH);
        const float4* hh = (const float4*)hn;
        float a = b_fc[j];
#pragma unroll
        for (int k = 0; k < 32; k++) {
            float4 w = wr[k];
            float4 x = hh[k];
            a += w.x * x.x + w.y * x.y + w.z * x.z + w.w * x.w;
        }
        out[g * 16 + j] = a;
    }
}

// ---------------- host-side symbol address helpers ----------------
static __half* get_x16_ptr() {
    static __half* p = nullptr;
    if (!p) cudaGetSymbolAddress((void**)&p, g_x16);
    return p;
}
static __half* get_h16_ptr() {
    static __half* p = nullptr;
    if (!p) cudaGetSymbolAddress((void**)&p, g_h16);
    return p;
}
static __half2* get_t_ptr() {
    static __half2* p = nullptr;
    if (!p) cudaGetSymbolAddress((void**)&p, g_t);
    return p;
}
static __half* get_w16t_ptr() {
    static __half* p = nullptr;
    if (!p) cudaGetSymbolAddress((void**)&p, g_w16t);
    return p;
}

// ---------------- launch ----------------
extern "C" void kernel_launch(void* const* d_in, const int* in_sizes, int n_in,
                              void* d_out, int out_size) {
    const float* x     = (const float*)d_in[0];
    const int*   eidx  = (const int*)d_in[1];      // [2, E]
    const int*   batch = (const int*)d_in[2];
    const float* Ws    = (const float*)d_in[3];    // [3,128,128]
    const float* bs    = (const float*)d_in[4];
    const float* gam   = (const float*)d_in[5];
    const float* bet   = (const float*)d_in[6];
    const float* rms   = (const float*)d_in[7];
    const float* rvs   = (const float*)d_in[8];
    const float* W_ih  = (const float*)d_in[9];
    // d_in[10] = W_hh (unused: h0 = c0 = 0)
    const float* b_ih  = (const float*)d_in[11];
    const float* b_hh  = (const float*)d_in[12];
    const float* W_fc  = (const float*)d_in[13];
    const float* b_fc  = (const float*)d_in[14];
    float* out = (float*)d_out;

    const int* src = eidx;
    const int* dst = eidx + EE;

    __half*  x16   = get_x16_ptr();
    __half*  h16   = get_h16_ptr();
    __half2* t_ptr = get_t_ptr();
    __half*  w16t  = get_w16t_ptr();

    static cudaStream_t s2 = nullptr;
    static cudaEvent_t ev_fork = nullptr, ev_join = nullptr;
    if (!s2) {
        cudaStreamCreateWithFlags(&s2, cudaStreamNonBlocking);
        cudaEventCreateWithFlags(&ev_fork, cudaEventDisableTiming);
        cudaEventCreateWithFlags(&ev_join, cudaEventDisableTiming);
        cudaFuncSetAttribute(gemm_mma_kernel,
                             cudaFuncAttributeMaxDynamicSharedMemorySize, GEMM_SMEM);
    }

    // fork: CSR build chain on s2
    cudaEventRecord(ev_fork, 0);
    cudaStreamWaitEvent(s2, ev_fork, 0);

    init_kernel<<<(NN + 255) / 256, 256, 0, s2>>>();
    count_kernel<<<(EE + 255) / 256, 256, 0, s2>>>(dst);
    dinv_kernel<<<(NN + 255) / 256, 256, 0, s2>>>();
    scan_reduce_kernel<<<SCAN_BLOCKS, SCAN_CHUNK, 0, s2>>>();
    scan_spine_kernel<<<1, 128, 0, s2>>>();
    scan_apply_kernel<<<SCAN_BLOCKS, SCAN_CHUNK, 0, s2>>>();
    scatter_kernel<<<(EE + 255) / 256, 256, 0, s2>>>(src, dst);
    bounds_kernel<<<1, 256, 0, s2>>>(batch);
    cudaEventRecord(ev_join, s2);

    // main stream: conversions + layer pipeline
    {
        dim3 wgrid((HH * HH + 255) / 256, LL);
        convert_w_kernel<<<wgrid, 256>>>(Ws);
    }
    convert_x_kernel<<<(NN * HH / 2 + 255) / 256, 256>>>(x);

    int gemm_blocks = (NN + 127) / 128;
    int spmm_blocks = (NN * 32 + 255) / 256;

    gemm_mma_kernel<<<gemm_blocks, 256, GEMM_SMEM>>>(x16, w16t, t_ptr, NN);
    cudaStreamWaitEvent(0, ev_join, 0);                       // join CSR build
    spmm_kernel<<<spmm_blocks, 256>>>(bs, gam, bet, rms, rvs);

    for (int l = 1; l < LL; l++) {
        gemm_mma_kernel<<<gemm_blocks, 256, GEMM_SMEM>>>(h16, w16t + (size_t)l * HH * HH,
                                                         t_ptr, NN);
        spmm_kernel<<<spmm_blocks, 256>>>(bs + l * HH, gam + l * HH, bet + l * HH,
                                          rms + l * HH, rvs + l * HH);
    }
    pool_lstm_kernel<<<GG, 128>>>(W_ih, b_ih, b_hh, W_fc, b_fc, out);
}

// round 8
// speedup vs baseline: 1.4364x; 1.1407x over previous
#include <cuda_runtime.h>
#include <cuda_fp16.h>
#include <math.h>

#define NN 100000
#define EE 1600000
#define HH 128
#define GG 128
#define LL 3
#define BN_EPS 1e-5f

#define SCAN_CHUNK 1024
#define SCAN_BLOCKS ((NN + SCAN_CHUNK - 1) / SCAN_CHUNK)   // 98

#define APAD 136                       // padded row length in halves (conflict-free)
#define GEMM_SMEM (2 * 128 * APAD * 2) // 69632 bytes

// ---------------- scratch (device globals; no allocation) ----------------
__device__ int   g_deg[NN];
__device__ int   g_fill[NN];
__device__ int   g_rowptr[NN + 1];
__device__ int   g_colidx[EE];
__device__ int   g_gstart[GG + 1];
__device__ int   g_bsum[SCAN_BLOCKS];
__device__ float g_dinv[NN];
__device__ __half2 g_x16[(size_t)NN * HH / 2];  // fp16 input features
__device__ __half2 g_t[(size_t)NN * HH / 2];    // post-GEMM features, rows pre-scaled by dinv
__device__ __half2 g_h16[(size_t)NN * HH / 2];  // post-SpMM activations (fp16)
__device__ __half  g_w16t[(size_t)LL * HH * HH]; // W transposed [l][n][k] fp16

// ---------------- CSR build ----------------
__global__ void init_kernel() {
    int i = blockIdx.x * blockDim.x + threadIdx.x;
    if (i < NN) { g_deg[i] = 1; g_fill[i] = 0; }   // self-loop counts 1
}

__global__ void count_kernel(const int* __restrict__ dst) {
    int e = blockIdx.x * blockDim.x + threadIdx.x;
    if (e < EE) atomicAdd(&g_deg[dst[e]], 1);
}

__global__ void dinv_kernel() {
    int i = blockIdx.x * blockDim.x + threadIdx.x;
    if (i < NN) g_dinv[i] = rsqrtf((float)g_deg[i]);
}

__device__ __forceinline__ int warp_incl_scan(int v, unsigned lane) {
#pragma unroll
    for (int o = 1; o < 32; o <<= 1) {
        int t = __shfl_up_sync(0xffffffffu, v, o);
        if (lane >= o) v += t;
    }
    return v;
}

__global__ void scan_reduce_kernel() {
    __shared__ int wsum[32];
    int tid = threadIdx.x;
    unsigned lane = tid & 31;
    int wid = tid >> 5;
    int i = blockIdx.x * SCAN_CHUNK + tid;
    int v = (i < NN) ? (g_deg[i] - 1) : 0;
#pragma unroll
    for (int o = 16; o > 0; o >>= 1) v += __shfl_down_sync(0xffffffffu, v, o);
    if (lane == 0) wsum[wid] = v;
    __syncthreads();
    if (wid == 0) {
        int w = wsum[lane];
#pragma unroll
        for (int o = 16; o > 0; o >>= 1) w += __shfl_down_sync(0xffffffffu, w, o);
        if (lane == 0) g_bsum[blockIdx.x] = w;
    }
}

__global__ void scan_spine_kernel() {
    __shared__ int wtot[4];
    int tid = threadIdx.x;              // 0..127
    unsigned lane = tid & 31;
    int wid = tid >> 5;
    int v = (tid < SCAN_BLOCKS) ? g_bsum[tid] : 0;
    int incl = warp_incl_scan(v, lane);
    if (lane == 31) wtot[wid] = incl;
    __syncthreads();
    int off = 0;
    for (int w = 0; w < wid; w++) off += wtot[w];
    if (tid < SCAN_BLOCKS) g_bsum[tid] = off + incl - v;   // exclusive
    if (tid == 127) g_rowptr[NN] = off + incl;             // grand total
}

__global__ void scan_apply_kernel() {
    __shared__ int wsum[32];
    int tid = threadIdx.x;
    unsigned lane = tid & 31;
    int wid = tid >> 5;
    int i = blockIdx.x * SCAN_CHUNK + tid;
    int v = (i < NN) ? (g_deg[i] - 1) : 0;
    int incl = warp_incl_scan(v, lane);
    if (lane == 31) wsum[wid] = incl;
    __syncthreads();
    int woff = 0;
    for (int w = 0; w < wid; w++) woff += wsum[w];
    if (i < NN) g_rowptr[i] = g_bsum[blockIdx.x] + woff + incl - v;
}

__global__ void scatter_kernel(const int* __restrict__ src, const int* __restrict__ dst) {
    int e = blockIdx.x * blockDim.x + threadIdx.x;
    if (e < EE) {
        int d = dst[e];
        int p = g_rowptr[d] + atomicAdd(&g_fill[d], 1);
        g_colidx[p] = src[e];
    }
}

__global__ void bounds_kernel(const int* __restrict__ batch) {
    int g = blockIdx.x * blockDim.x + threadIdx.x;
    if (g > GG) return;
    int lo = 0, hi = NN;
    while (lo < hi) {
        int m = (lo + hi) >> 1;
        if (batch[m] < g) lo = m + 1; else hi = m;
    }
    g_gstart[g] = lo;
}

// ---------------- conversions ----------------
__global__ void convert_x_kernel(const float* __restrict__ x) {
    int i = blockIdx.x * blockDim.x + threadIdx.x;
    if (i < NN * HH / 2) {
        float2 f = ((const float2*)x)[i];
        g_x16[i] = __floats2half2_rn(f.x, f.y);
    }
}

__global__ void convert_w_kernel(const float* __restrict__ Ws) {
    int i = blockIdx.x * blockDim.x + threadIdx.x;   // 0..HH*HH-1
    int l = blockIdx.y;
    if (i < HH * HH) {
        int k = i >> 7, n = i & 127;
        g_w16t[(size_t)l * HH * HH + n * HH + k] = __float2half(Ws[(size_t)l * HH * HH + i]);
    }
}

// ---------------- tensor-core GEMM (ldmatrix): C = A @ W, rows optionally scaled ----------------
extern __shared__ __align__(16) char gemm_smem[];

__global__ void __launch_bounds__(256)
gemm_mma_kernel(const __half* __restrict__ A, const __half* __restrict__ Wt,
                __half2* __restrict__ C2, const float* __restrict__ rowscale, int n) {
    __half* As = (__half*)gemm_smem;                       // [128][APAD]
    __half* Bs = (__half*)(gemm_smem + 128 * APAD * 2);    // [128][APAD] (Wt: [n][k])

    int tid = threadIdx.x;
    int r0 = blockIdx.x * 128;

    const uint4* Ag = (const uint4*)A;
    const uint4* Wg = (const uint4*)Wt;
    uint4* As4 = (uint4*)As;
    uint4* Bs4 = (uint4*)Bs;
#pragma unroll
    for (int i = 0; i < 8; i++) {
        int lin = tid + i * 256;          // 0..2047
        int row = lin >> 4, c = lin & 15;
        uint4 v = make_uint4(0, 0, 0, 0);
        if (r0 + row < n) v = Ag[(size_t)(r0 + row) * 16 + c];
        As4[row * 17 + c] = v;
        Bs4[row * 17 + c] = Wg[row * 16 + c];
    }
    __syncthreads();

    int lane = tid & 31, warp = tid >> 5;
    int wm = (warp & 3) * 32;
    int wn = (warp >> 2) * 64;
    int g = lane >> 2, tg = lane & 3;
    int t3 = lane >> 3, r8 = lane & 7;

    // ldmatrix per-lane base addresses
    unsigned As_base = (unsigned)__cvta_generic_to_shared(As);
    unsigned Bs_base = (unsigned)__cvta_generic_to_shared(Bs);
    // A x4 tiles: (m0-7,k0-7),(m8-15,k0-7),(m0-7,k8-15),(m8-15,k8-15)
    unsigned a_addr[2];
#pragma unroll
    for (int mt = 0; mt < 2; mt++) {
        int row = wm + mt * 16 + (t3 & 1) * 8 + r8;
        int col = (t3 >> 1) * 8;
        a_addr[mt] = As_base + (row * APAD + col) * 2;
    }
    // B x4 tiles per nt-pair: (nt0,k0-7),(nt0,k8-15),(nt1,k0-7),(nt1,k8-15)
    unsigned b_addr[4];
#pragma unroll
    for (int ntp = 0; ntp < 4; ntp++) {
        int row = wn + ntp * 16 + (t3 >> 1) * 8 + r8;
        int col = (t3 & 1) * 8;
        b_addr[ntp] = Bs_base + (row * APAD + col) * 2;
    }

    float c[2][8][4];
#pragma unroll
    for (int mt = 0; mt < 2; mt++)
#pragma unroll
        for (int nt = 0; nt < 8; nt++)
#pragma unroll
            for (int q = 0; q < 4; q++) c[mt][nt][q] = 0.f;

#pragma unroll
    for (int ks = 0; ks < 8; ks++) {
        unsigned koff = ks * 32;   // 16 halves = 32 bytes
        unsigned a[2][4];
#pragma unroll
        for (int mt = 0; mt < 2; mt++) {
            asm volatile("ldmatrix.sync.aligned.m8n8.x4.shared.b16 {%0,%1,%2,%3}, [%4];"
                         : "=r"(a[mt][0]), "=r"(a[mt][1]), "=r"(a[mt][2]), "=r"(a[mt][3])
                         : "r"(a_addr[mt] + koff));
        }
#pragma unroll
        for (int ntp = 0; ntp < 4; ntp++) {
            unsigned b00, b01, b10, b11;
            asm volatile("ldmatrix.sync.aligned.m8n8.x4.shared.b16 {%0,%1,%2,%3}, [%4];"
                         : "=r"(b00), "=r"(b01), "=r"(b10), "=r"(b11)
                         : "r"(b_addr[ntp] + koff));
#pragma unroll
            for (int mt = 0; mt < 2; mt++) {
                asm volatile(
                    "mma.sync.aligned.m16n8k16.row.col.f32.f16.f16.f32 "
                    "{%0,%1,%2,%3}, {%4,%5,%6,%7}, {%8,%9}, {%0,%1,%2,%3};"
                    : "+f"(c[mt][2 * ntp][0]), "+f"(c[mt][2 * ntp][1]),
                      "+f"(c[mt][2 * ntp][2]), "+f"(c[mt][2 * ntp][3])
                    : "r"(a[mt][0]), "r"(a[mt][1]), "r"(a[mt][2]), "r"(a[mt][3]),
                      "r"(b00), "r"(b01));
                asm volatile(
                    "mma.sync.aligned.m16n8k16.row.col.f32.f16.f16.f32 "
                    "{%0,%1,%2,%3}, {%4,%5,%6,%7}, {%8,%9}, {%0,%1,%2,%3};"
                    : "+f"(c[mt][2 * ntp + 1][0]), "+f"(c[mt][2 * ntp + 1][1]),
                      "+f"(c[mt][2 * ntp + 1][2]), "+f"(c[mt][2 * ntp + 1][3])
                    : "r"(a[mt][0]), "r"(a[mt][1]), "r"(a[mt][2]), "r"(a[mt][3]),
                      "r"(b10), "r"(b11));
            }
        }
    }

    // epilogue: optional per-row scale, fp32 -> fp16
#pragma unroll
    for (int mt = 0; mt < 2; mt++) {
        int rb = r0 + wm + mt * 16;
        int r_lo = rb + g, r_hi = rb + g + 8;
        float s_lo = 1.f, s_hi = 1.f;
        if (rowscale) {
            if (r_lo < n) s_lo = rowscale[r_lo];
            if (r_hi < n) s_hi = rowscale[r_hi];
        }
#pragma unroll
        for (int nt = 0; nt < 8; nt++) {
            int col2 = ((wn + nt * 8) >> 1) + tg;
            if (r_lo < n) C2[(size_t)r_lo * 64 + col2] =
                __floats2half2_rn(s_lo * c[mt][nt][0], s_lo * c[mt][nt][1]);
            if (r_hi < n) C2[(size_t)r_hi * 64 + col2] =
                __floats2half2_rn(s_hi * c[mt][nt][2], s_hi * c[mt][nt][3]);
        }
    }
}

// ---------------- SpMM + bias + BN + ReLU (warp per node) ----------------
// Rows of g_t are pre-scaled by dinv[row]; per edge: pure row add. Final *dv.
// prescale_out: multiply output by dinv[v] (feeds next GEMM).
__global__ void spmm_kernel(const float* __restrict__ bias, const float* __restrict__ gamma,
                            const float* __restrict__ beta, const float* __restrict__ rm,
                            const float* __restrict__ rv, int prescale_out) {
    int warp = (blockIdx.x * blockDim.x + threadIdx.x) >> 5;
    if (warp >= NN) return;
    int lane = threadIdx.x & 31;
    int v = warp;
    float dv = g_dinv[v];
    const uint2* t8 = (const uint2*)g_t;   // 8 bytes = 4 fp16 features

    // self-loop: t'[v] is just another summand
    uint2 xs = t8[(size_t)v * 32 + lane];
    float2 f01 = __half22float2(*(__half2*)&xs.x);
    float2 f23 = __half22float2(*(__half2*)&xs.y);
    float4 acc = make_float4(f01.x, f01.y, f23.x, f23.y);

    int j = g_rowptr[v], end = g_rowptr[v + 1];
    for (; j + 7 < end; j += 8) {
        int c0 = g_colidx[j],     c1 = g_colidx[j + 1], c2 = g_colidx[j + 2], c3 = g_colidx[j + 3];
        int c4 = g_colidx[j + 4], c5 = g_colidx[j + 5], c6 = g_colidx[j + 6], c7 = g_colidx[j + 7];
        uint2 x0 = t8[(size_t)c0 * 32 + lane];
        uint2 x1 = t8[(size_t)c1 * 32 + lane];
        uint2 x2 = t8[(size_t)c2 * 32 + lane];
        uint2 x3 = t8[(size_t)c3 * 32 + lane];
        uint2 x4 = t8[(size_t)c4 * 32 + lane];
        uint2 x5 = t8[(size_t)c5 * 32 + lane];
        uint2 x6 = t8[(size_t)c6 * 32 + lane];
        uint2 x7 = t8[(size_t)c7 * 32 + lane];
        float2 a0 = __half22float2(*(__half2*)&x0.x), b0 = __half22float2(*(__half2*)&x0.y);
        float2 a1 = __half22float2(*(__half2*)&x1.x), b1 = __half22float2(*(__half2*)&x1.y);
        float2 a2 = __half22float2(*(__half2*)&x2.x), b2 = __half22float2(*(__half2*)&x2.y);
        float2 a3 = __half22float2(*(__half2*)&x3.x), b3 = __half22float2(*(__half2*)&x3.y);
        float2 a4 = __half22float2(*(__half2*)&x4.x), b4 = __half22float2(*(__half2*)&x4.y);
        float2 a5 = __half22float2(*(__half2*)&x5.x), b5 = __half22float2(*(__half2*)&x5.y);
        float2 a6 = __half22float2(*(__half2*)&x6.x), b6 = __half22float2(*(__half2*)&x6.y);
        float2 a7 = __half22float2(*(__half2*)&x7.x), b7 = __half22float2(*(__half2*)&x7.y);
        acc.x += (a0.x + a1.x) + (a2.x + a3.x) + (a4.x + a5.x) + (a6.x + a7.x);
        acc.y += (a0.y + a1.y) + (a2.y + a3.y) + (a4.y + a5.y) + (a6.y + a7.y);
        acc.z += (b0.x + b1.x) + (b2.x + b3.x) + (b4.x + b5.x) + (b6.x + b7.x);
        acc.w += (b0.y + b1.y) + (b2.y + b3.y) + (b4.y + b5.y) + (b6.y + b7.y);
    }
    for (; j + 3 < end; j += 4) {
        int c0 = g_colidx[j], c1 = g_colidx[j + 1], c2 = g_colidx[j + 2], c3 = g_colidx[j + 3];
        uint2 x0 = t8[(size_t)c0 * 32 + lane];
        uint2 x1 = t8[(size_t)c1 * 32 + lane];
        uint2 x2 = t8[(size_t)c2 * 32 + lane];
        uint2 x3 = t8[(size_t)c3 * 32 + lane];
        float2 a0 = __half22float2(*(__half2*)&x0.x), b0 = __half22float2(*(__half2*)&x0.y);
        float2 a1 = __half22float2(*(__half2*)&x1.x), b1 = __half22float2(*(__half2*)&x1.y);
        float2 a2 = __half22float2(*(__half2*)&x2.x), b2 = __half22float2(*(__half2*)&x2.y);
        float2 a3 = __half22float2(*(__half2*)&x3.x), b3 = __half22float2(*(__half2*)&x3.y);
        acc.x += (a0.x + a1.x) + (a2.x + a3.x);
        acc.y += (a0.y + a1.y) + (a2.y + a3.y);
        acc.z += (b0.x + b1.x) + (b2.x + b3.x);
        acc.w += (b0.y + b1.y) + (b2.y + b3.y);
    }
    for (; j < end; ++j) {
        int cc = g_colidx[j];
        uint2 xx = t8[(size_t)cc * 32 + lane];
        float2 a = __half22float2(*(__half2*)&xx.x);
        float2 b = __half22float2(*(__half2*)&xx.y);
        acc.x += a.x; acc.y += a.y; acc.z += b.x; acc.w += b.y;
    }

    float4 b  = *(const float4*)(bias  + lane * 4);
    float4 gm = *(const float4*)(gamma + lane * 4);
    float4 bt = *(const float4*)(beta  + lane * 4);
    float4 m  = *(const float4*)(rm    + lane * 4);
    float4 vv = *(const float4*)(rv    + lane * 4);

    float s0 = gm.x * rsqrtf(vv.x + BN_EPS);
    float s1 = gm.y * rsqrtf(vv.y + BN_EPS);
    float s2 = gm.z * rsqrtf(vv.z + BN_EPS);
    float s3 = gm.w * rsqrtf(vv.w + BN_EPS);

    float o0 = fmaxf((dv * acc.x + b.x - m.x) * s0 + bt.x, 0.f);
    float o1 = fmaxf((dv * acc.y + b.y - m.y) * s1 + bt.y, 0.f);
    float o2 = fmaxf((dv * acc.z + b.z - m.z) * s2 + bt.z, 0.f);
    float o3 = fmaxf((dv * acc.w + b.w - m.w) * s3 + bt.w, 0.f);

    if (prescale_out) { o0 *= dv; o1 *= dv; o2 *= dv; o3 *= dv; }

    __half2 p0 = __floats2half2_rn(o0, o1);
    __half2 p1 = __floats2half2_rn(o2, o3);
    uint2 u; u.x = *(unsigned*)&p0; u.y = *(unsigned*)&p1;
    ((uint2*)g_h16)[(size_t)v * 32 + lane] = u;
}

// ---------------- pool + LSTM + FC (block per graph) ----------------
__device__ __forceinline__ float sigmoidf_(float x) { return 1.f / (1.f + expf(-x)); }

__global__ void pool_lstm_kernel(const float* __restrict__ W_ih, const float* __restrict__ b_ih,
                                 const float* __restrict__ b_hh, const float* __restrict__ W_fc,
                                 const float* __restrict__ b_fc, float* __restrict__ out) {
    int g = blockIdx.x;
    int j = threadIdx.x;  // 0..127
    __shared__ __align__(16) float p[HH];
    __shared__ __align__(16) float hn[HH];

    const __half* hb = (const __half*)g_h16;
    int s = g_gstart[g], e = g_gstart[g + 1];
    float sum = 0.f;
    int n = s;
    for (; n + 3 < e; n += 4) {
        sum += __half2float(hb[(size_t)n * HH + j]) + __half2float(hb[(size_t)(n + 1) * HH + j])
             + __half2float(hb[(size_t)(n + 2) * HH + j]) + __half2float(hb[(size_t)(n + 3) * HH + j]);
    }
    for (; n < e; ++n) sum += __half2float(hb[(size_t)n * HH + j]);
    float cnt = (float)((e - s) > 0 ? (e - s) : 1);
    p[j] = sum / cnt;
    __syncthreads();

    float gate[4];
#pragma unroll
    for (int q = 0; q < 4; q++) {
        const float4* wr = (const float4*)(W_ih + (size_t)(q * HH + j) * HH);
        const float4* pp = (const float4*)p;
        float a = 0.f;
#pragma unroll
        for (int k = 0; k < 32; k++) {
            float4 w = wr[k];
            float4 x = pp[k];
            a += w.x * x.x + w.y * x.y + w.z * x.z + w.w * x.w;
        }
        gate[q] = a + b_ih[q * HH + j] + b_hh[q * HH + j];
    }
    float iv = sigmoidf_(gate[0]);
    float gv = tanhf(gate[2]);
    float ov = sigmoidf_(gate[3]);
    float c = iv * gv;
    hn[j] = ov * tanhf(c);
    __syncthreads();

    if (j < 16) {
        const float4* wr = (const float4*)(W_fc + (size_t)j * HH);
        const float4* hh = (const float4*)hn;
        float a = b_fc[j];
#pragma unroll
        for (int k = 0; k < 32; k++) {
            float4 w = wr[k];
            float4 x = hh[k];
            a += w.x * x.x + w.y * x.y + w.z * x.z + w.w * x.w;
        }
        out[g * 16 + j] = a;
    }
}

// ---------------- host-side symbol address helpers ----------------
static __half* get_x16_ptr() {
    static __half* p = nullptr;
    if (!p) cudaGetSymbolAddress((void**)&p, g_x16);
    return p;
}
static __half* get_h16_ptr() {
    static __half* p = nullptr;
    if (!p) cudaGetSymbolAddress((void**)&p, g_h16);
    return p;
}
static __half2* get_t_ptr() {
    static __half2* p = nullptr;
    if (!p) cudaGetSymbolAddress((void**)&p, g_t);
    return p;
}
static __half* get_w16t_ptr() {
    static __half* p = nullptr;
    if (!p) cudaGetSymbolAddress((void**)&p, g_w16t);
    return p;
}
static float* get_dinv_ptr() {
    static float* p = nullptr;
    if (!p) cudaGetSymbolAddress((void**)&p, g_dinv);
    return p;
}

// ---------------- launch ----------------
extern "C" void kernel_launch(void* const* d_in, const int* in_sizes, int n_in,
                              void* d_out, int out_size) {
    const float* x     = (const float*)d_in[0];
    const int*   eidx  = (const int*)d_in[1];      // [2, E]
    const int*   batch = (const int*)d_in[2];
    const float* Ws    = (const float*)d_in[3];    // [3,128,128]
    const float* bs    = (const float*)d_in[4];
    const float* gam   = (const float*)d_in[5];
    const float* bet   = (const float*)d_in[6];
    const float* rms   = (const float*)d_in[7];
    const float* rvs   = (const float*)d_in[8];
    const float* W_ih  = (const float*)d_in[9];
    // d_in[10] = W_hh (unused: h0 = c0 = 0)
    const float* b_ih  = (const float*)d_in[11];
    const float* b_hh  = (const float*)d_in[12];
    const float* W_fc  = (const float*)d_in[13];
    const float* b_fc  = (const float*)d_in[14];
    float* out = (float*)d_out;

    const int* src = eidx;
    const int* dst = eidx + EE;

    __half*  x16   = get_x16_ptr();
    __half*  h16   = get_h16_ptr();
    __half2* t_ptr = get_t_ptr();
    __half*  w16t  = get_w16t_ptr();
    float*   dinv  = get_dinv_ptr();

    static cudaStream_t s2 = nullptr;
    static cudaEvent_t ev_fork = nullptr, ev_dinv = nullptr, ev_join = nullptr;
    if (!s2) {
        cudaStreamCreateWithFlags(&s2, cudaStreamNonBlocking);
        cudaEventCreateWithFlags(&ev_fork, cudaEventDisableTiming);
        cudaEventCreateWithFlags(&ev_dinv, cudaEventDisableTiming);
        cudaEventCreateWithFlags(&ev_join, cudaEventDisableTiming);
        cudaFuncSetAttribute(gemm_mma_kernel,
                             cudaFuncAttributeMaxDynamicSharedMemorySize, GEMM_SMEM);
    }

    // fork: CSR build chain on s2
    cudaEventRecord(ev_fork, 0);
    cudaStreamWaitEvent(s2, ev_fork, 0);

    init_kernel<<<(NN + 255) / 256, 256, 0, s2>>>();
    count_kernel<<<(EE + 255) / 256, 256, 0, s2>>>(dst);
    dinv_kernel<<<(NN + 255) / 256, 256, 0, s2>>>();
    cudaEventRecord(ev_dinv, s2);
    scan_reduce_kernel<<<SCAN_BLOCKS, SCAN_CHUNK, 0, s2>>>();
    scan_spine_kernel<<<1, 128, 0, s2>>>();
    scan_apply_kernel<<<SCAN_BLOCKS, SCAN_CHUNK, 0, s2>>>();
    scatter_kernel<<<(EE + 255) / 256, 256, 0, s2>>>(src, dst);
    bounds_kernel<<<1, 256, 0, s2>>>(batch);
    cudaEventRecord(ev_join, s2);

    // main stream: conversions overlap count phase
    {
        dim3 wgrid((HH * HH + 255) / 256, LL);
        convert_w_kernel<<<wgrid, 256>>>(Ws);
    }
    convert_x_kernel<<<(NN * HH / 2 + 255) / 256, 256>>>(x);

    int gemm_blocks = (NN + 127) / 128;
    int spmm_blocks = (NN * 32 + 255) / 256;

    cudaStreamWaitEvent(0, ev_dinv, 0);                       // gemm0 scales rows by dinv
    gemm_mma_kernel<<<gemm_blocks, 256, GEMM_SMEM>>>(x16, w16t, t_ptr, dinv, NN);
    cudaStreamWaitEvent(0, ev_join, 0);                       // join CSR build
    spmm_kernel<<<spmm_blocks, 256>>>(bs, gam, bet, rms, rvs, 1);

    for (int l = 1; l < LL; l++) {
        // h16 rows already pre-scaled by dinv (except last layer, flag below)
        gemm_mma_kernel<<<gemm_blocks, 256, GEMM_SMEM>>>(h16, w16t + (size_t)l * HH * HH,
                                                         t_ptr, nullptr, NN);
        spmm_kernel<<<spmm_blocks, 256>>>(bs + l * HH, gam + l * HH, bet + l * HH,
                                          rms + l * HH, rvs + l * HH, (l < LL - 1) ? 1 : 0);
    }
    pool_lstm_kernel<<<GG, 128>>>(W_ih, b_ih, b_hh, W_fc, b_fc, out);
}